// round 11
// baseline (speedup 1.0000x reference)
#include <cuda_runtime.h>
#include <cuda_fp16.h>
#include <cstdint>

#define LQ   9216
#define KD   144
#define CCH  16
#define HH   96
#define WW   96
#define BB   2
#define TOUT (BB*CCH*192*192) /* 1179648 */
#define SOUT (BB*LQ)          /* 18432   */
#define NT   72               /* tiles of 128 patches */
#define NKB  9                /* hi-only k16 blocks per tile */
#define TILE_U32 9216         /* packed u32 per tile image (9*1024) */
#define NCAND 96              /* per-query candidate slots: 16 writers x 6 */

__device__ __align__(16) uint16_t g_raw_lr [BB*LQ*288];
__device__ __align__(16) uint16_t g_raw_ref[BB*LQ*288];
__device__ float g_anorm[BB*LQ];
__device__ __align__(16) uint32_t g_A[BB*NT*TILE_U32];
__device__ __align__(16) uint32_t g_B[BB*NT*TILE_U32];
__device__ uint32_t g_cand[BB*LQ*NCAND];
__device__ int g_S[BB*LQ];

// ------------------------------------------------------------ PTX helpers ---
__device__ __forceinline__ uint32_t smem_u32(const void* p) {
  uint32_t a;
  asm("{ .reg .u64 t; cvta.to.shared.u64 t, %1; cvt.u32.u64 %0, t; }"
      : "=r"(a) : "l"(p));
  return a;
}
__device__ __forceinline__ void mbar_init(uint32_t a, uint32_t cnt) {
  asm volatile("mbarrier.init.shared.b64 [%0], %1;" :: "r"(a), "r"(cnt) : "memory");
}
__device__ __forceinline__ void mbar_arrive(uint32_t a) {
  asm volatile("mbarrier.arrive.shared.b64 _, [%0];" :: "r"(a) : "memory");
}
__device__ __forceinline__ void mbar_wait(uint32_t a, uint32_t parity) {
  asm volatile(
      "{\n\t.reg .pred P;\n\t"
      "WL_%=:\n\t"
      "mbarrier.try_wait.parity.acquire.cta.shared::cta.b64 P, [%0], %1, 0x989680;\n\t"
      "@P bra.uni WD_%=;\n\t"
      "bra.uni WL_%=;\n\t"
      "WD_%=:\n\t}"
      :: "r"(a), "r"(parity) : "memory");
}
__device__ __forceinline__ void cp16(uint32_t dst, const void* src) {
  asm volatile("cp.async.cg.shared.global [%0], [%1], 16;"
               :: "r"(dst), "l"(src) : "memory");
}
__device__ __forceinline__ void cp_commit() {
  asm volatile("cp.async.commit_group;" ::: "memory");
}
__device__ __forceinline__ void cp_wait0() {
  asm volatile("cp.async.wait_group 0;" ::: "memory");
}
__device__ __forceinline__ void mma_f16(float c[4], const uint32_t a[4],
                                        const uint32_t b[2]) {
  asm volatile(
      "mma.sync.aligned.m16n8k16.row.col.f32.f16.f16.f32 "
      "{%0,%1,%2,%3}, {%4,%5,%6,%7}, {%8,%9}, {%0,%1,%2,%3};"
      : "+f"(c[0]), "+f"(c[1]), "+f"(c[2]), "+f"(c[3])
      : "r"(a[0]), "r"(a[1]), "r"(a[2]), "r"(a[3]), "r"(b[0]), "r"(b[1]));
}
__device__ __forceinline__ void f16_split(float v, uint16_t& hi, uint16_t& lo) {
  uint16_t h;
  asm("cvt.rn.f16.f32 %0, %1;" : "=h"(h) : "f"(v));
  float hf;
  asm("cvt.f32.f16 %0, %1;" : "=f"(hf) : "h"(h));
  uint16_t l;
  asm("cvt.rn.f16.f32 %0, %1;" : "=h"(l) : "f"(v - hf));
  hi = h; lo = l;
}
__device__ __forceinline__ float f16u(uint16_t b) {
  float f;
  asm("cvt.f32.f16 %0, %1;" : "=f"(f) : "h"(b));
  return f;
}

// ---------------------------------------- prep: unfold + norm + fp16 split --
__global__ __launch_bounds__(256) void prep_kernel(
    const float* __restrict__ lrsr, const float* __restrict__ refsr) {
  int gw   = (blockIdx.x * 256 + threadIdx.x) >> 5;
  int lane = threadIdx.x & 31;
  if (gw >= 2 * BB * LQ) return;
  int sel = (gw >= BB * LQ) ? 1 : 0;
  int r = gw - sel * BB * LQ;
  int b = r / LQ, l = r - b * LQ;
  int y = l / WW, x = l - y * WW;
  const float* src = (sel ? refsr : lrsr) + (size_t)b * CCH * HH * WW;

  float v[5];
  float ss = 0.f;
  #pragma unroll
  for (int j = 0; j < 5; j++) {
    int f = lane + j * 32;
    float val = 0.f;
    if (f < KD) {
      int c = f / 9, k9 = f - c * 9, ki = k9 / 3, kj = k9 - ki * 3;
      int iy = y + ki - 1, ix = x + kj - 1;
      if (iy >= 0 && iy < HH && ix >= 0 && ix < WW)
        val = src[(c * HH + iy) * WW + ix];
    }
    v[j] = val;
    ss += val * val;
  }
  #pragma unroll
  for (int o = 16; o; o >>= 1) ss += __shfl_xor_sync(0xffffffffu, ss, o);
  uint16_t* dst;
  if (sel) {
    float inv = 1.0f / fmaxf(sqrtf(ss), 1e-12f);
    #pragma unroll
    for (int j = 0; j < 5; j++) v[j] *= inv;
    dst = g_raw_ref;
  } else {
    if (lane == 0) g_anorm[r] = sqrtf(ss);
    dst = g_raw_lr;
  }
  dst += (size_t)r * 288;
  #pragma unroll
  for (int j = 0; j < 5; j++) {
    int f = lane + j * 32;
    if (f < KD) {
      uint16_t h, lo;
      f16_split(v[j], h, lo);
      dst[f]       = h;
      dst[144 + f] = lo;
    }
  }
}

// ------------------------- pack hi blocks into m16n8k16 fragment layouts ----
__global__ __launch_bounds__(256) void pack_kernel() {
  int ti  = blockIdx.x;                  // b*NT + tile
  int isB = blockIdx.y;
  const uint32_t* raw32 = reinterpret_cast<const uint32_t*>(
      (isB ? g_raw_ref : g_raw_lr) + (size_t)ti * 128 * 288);
  uint4* dst = reinterpret_cast<uint4*>(
      (isB ? g_B : g_A) + (size_t)ti * TILE_U32);
  for (int o4 = threadIdx.x; o4 < TILE_U32 / 4; o4 += 256) {
    int kb = o4 >> 8, rr = o4 & 255;     // 256 uint4 per 4KB block, kb<9
    uint4 val;
    if (isB) {
      int c2 = rr & 1, n = rr >> 1;
      int q = n * 144 + kb * 8 + 2 * c2;
      val.x = raw32[q];     val.y = raw32[q + 4];
      val.z = raw32[q + 1]; val.w = raw32[q + 5];
    } else {
      int c = rr & 3, g = (rr >> 2) & 7, mg = rr >> 5;
      int m = mg * 16 + g;
      int q = kb * 8 + c;
      val.x = raw32[m * 144 + q];       val.y = raw32[(m + 8) * 144 + q];
      val.z = raw32[m * 144 + q + 4];   val.w = raw32[(m + 8) * 144 + q + 4];
    }
    dst[o4] = val;
  }
}

// -------------------------------------------------- clear candidate lists ---
__global__ __launch_bounds__(256) void clear_kernel() {
  int i = blockIdx.x * 256 + threadIdx.x;
  if (i < BB * LQ * NCAND) g_cand[i] = 0u;
}

// ----------------------------- phase 1: hi-only argmax GEMM + candidates ----
#define SM_A   0          /* 36864 B: resident A hi image */
#define SM_B   36864      /* ring: 8 x 4096 B -> ends 69632 */
#define SM_MB  69632      /* mbarriers */
#define SM_RV  69760      /* 2048 B reduce vals */
#define SM_RI  71808      /* 2048 B reduce idx  */
#define SMEM_TOTAL 73856

__global__ __launch_bounds__(384, 1) void argmax_mma() {
  extern __shared__ __align__(16) char smem[];
  uint32_t sb = smem_u32(smem);
  int tid = threadIdx.x, wid = tid >> 5, lane = tid & 31;
  int cta = blockIdx.x;
  int b = cta / NT, qt = cta - b * NT;
  const uint32_t* Atile = g_A + (size_t)cta * TILE_U32;
  const uint32_t* Bbase = g_B + (size_t)b * NT * TILE_U32;

  uint32_t mb_full  = sb + SM_MB;        // 8 x 8B
  uint32_t mb_empty = sb + SM_MB + 64;   // 8 x 8B
  if (tid == 0) {
    for (int s = 0; s < 8; s++) {
      mbar_init(mb_full + 8 * s, 32);
      mbar_init(mb_empty + 8 * s, 256);
    }
  }
  for (int c = tid; c < TILE_U32 / 4; c += 384)
    cp16(sb + SM_A + c * 16, Atile + c * 4);
  cp_commit();
  cp_wait0();
  __syncthreads();

  if (wid >= 8) {
    int pw = wid - 8;
    for (int gblk = pw; gblk < NT * NKB; gblk += 4) {
      int s = gblk & 7, u = gblk >> 3;
      mbar_wait(mb_empty + 8 * s, (u & 1) ^ 1);
      const uint32_t* src = Bbase + (size_t)gblk * 1024;
      uint32_t slot = sb + SM_B + s * 4096;
      #pragma unroll
      for (int i = 0; i < 8; i++) {
        int c = i * 32 + lane;
        cp16(slot + c * 16, src + c * 4);
      }
      cp_commit();
      cp_wait0();
      mbar_arrive(mb_full + 8 * s);
    }
  } else {
    int wm = wid & 1, wn = (wid >> 1) & 3;
    float C[4][4][4];
    float bestv[8], margin[8];
    int besti[8], cnt[8];
    uint32_t candbase[8];
    #pragma unroll
    for (int sl = 0; sl < 8; sl++) {
      bestv[sl] = -3.4e38f; besti[sl] = 0; cnt[sl] = 0;
      int mf = sl >> 1, h = sl & 1;
      int m_local = wm * 64 + mf * 16 + (lane >> 2) + h * 8;
      int qg = b * LQ + qt * 128 + m_local;
      margin[sl] = 2e-3f * g_anorm[qg];
      candbase[sl] = (uint32_t)qg * NCAND + (wn * 4 + (lane & 3)) * 6;
    }

    uint32_t abase = sb + SM_A + (lane >> 2) * 64 + (lane & 3) * 16;
    uint32_t bbase = sb + SM_B + wn * 1024 + (lane >> 2) * 32 + (lane & 3) * 8;

    for (int t = 0; t < NT; t++) {
      #pragma unroll
      for (int mf = 0; mf < 4; mf++)
        #pragma unroll
        for (int nf = 0; nf < 4; nf++)
          #pragma unroll
          for (int c = 0; c < 4; c++) C[mf][nf][c] = 0.f;

      for (int kb = 0; kb < NKB; kb++) {
        int gblk = t * NKB + kb, s = gblk & 7, u = gblk >> 3;
        mbar_wait(mb_full + 8 * s, u & 1);
        uint32_t bslot = bbase + s * 4096;
        uint32_t breg[4][2];
        #pragma unroll
        for (int nf = 0; nf < 4; nf++)
          asm volatile("ld.shared.v2.b32 {%0,%1}, [%2];"
                       : "=r"(breg[nf][0]), "=r"(breg[nf][1])
                       : "r"(bslot + nf * 256));
        uint32_t areg[4][4];
        #pragma unroll
        for (int mf = 0; mf < 4; mf++)
          asm volatile("ld.shared.v4.b32 {%0,%1,%2,%3}, [%4];"
                       : "=r"(areg[mf][0]), "=r"(areg[mf][1]),
                         "=r"(areg[mf][2]), "=r"(areg[mf][3])
                       : "r"(abase + kb * 4096 + (wm * 4 + mf) * 512));
        #pragma unroll
        for (int mf = 0; mf < 4; mf++)
          #pragma unroll
          for (int nf = 0; nf < 4; nf++)
            mma_f16(C[mf][nf], areg[mf], breg[nf]);
        mbar_arrive(mb_empty + 8 * s);
      }
      // epilogue: running max + candidate ring append (rare branch)
      #pragma unroll
      for (int mf = 0; mf < 4; mf++) {
        #pragma unroll
        for (int h = 0; h < 2; h++) {
          int sl = mf * 2 + h;
          #pragma unroll
          for (int nf = 0; nf < 4; nf++) {
            #pragma unroll
            for (int cl = 0; cl < 2; cl++) {
              float vv = C[mf][nf][h * 2 + cl];
              if (vv > bestv[sl] - margin[sl]) {
                int n = t * 128 + wn * 32 + nf * 8 + (lane & 3) * 2 + cl;
                g_cand[candbase[sl] + cnt[sl]] = (uint32_t)(n + 1);
                cnt[sl] = (cnt[sl] == 5) ? 0 : cnt[sl] + 1;
                if (vv > bestv[sl]) { bestv[sl] = vv; besti[sl] = n; }
              }
            }
          }
        }
      }
    }
    // quad-lane reduce of approx best
    #pragma unroll
    for (int sl = 0; sl < 8; sl++) {
      float v = bestv[sl];
      int i = besti[sl];
      #pragma unroll
      for (int off = 1; off <= 2; off <<= 1) {
        float ov = __shfl_xor_sync(0xffffffffu, v, off);
        int oi = __shfl_xor_sync(0xffffffffu, i, off);
        if (ov > v || (ov == v && oi < i)) { v = ov; i = oi; }
      }
      bestv[sl] = v; besti[sl] = i;
    }
    if ((lane & 3) == 0) {
      float* rv = reinterpret_cast<float*>(smem + SM_RV);
      int* ri = reinterpret_cast<int*>(smem + SM_RI);
      #pragma unroll
      for (int sl = 0; sl < 8; sl++) {
        int m_local = wm * 64 + (sl >> 1) * 16 + (sl & 1) * 8 + (lane >> 2);
        rv[wn * 128 + m_local] = bestv[sl];
        ri[wn * 128 + m_local] = besti[sl];
      }
    }
  }

  __syncthreads();
  if (tid < 128) {
    const float* rv = reinterpret_cast<const float*>(smem + SM_RV);
    const int* ri = reinterpret_cast<const int*>(smem + SM_RI);
    float best = -3.4e38f; int bi = 0x7fffffff;
    #pragma unroll
    for (int wn = 0; wn < 4; wn++) {
      float v = rv[wn * 128 + tid];
      int i = ri[wn * 128 + tid];
      if (v > best || (v == best && i < bi)) { best = v; bi = i; }
    }
    g_S[b * LQ + qt * 128 + tid] = bi;
  }
}

// ------------------------------ phase 2: exact fp32 rescore of candidates ---
__global__ __launch_bounds__(256) void rescore_kernel(
    float* __restrict__ out_tail, int write_tail) {
  int gq = blockIdx.x * 8 + (threadIdx.x >> 5);
  int lane = threadIdx.x & 31;
  if (gq >= BB * LQ) return;
  int b = gq / LQ;

  // reconstruct query row a (exact fp32 = hi + lo)
  const uint16_t* araw = g_raw_lr + (size_t)gq * 288;
  float av[5];
  #pragma unroll
  for (int j = 0; j < 5; j++) {
    int f = lane + j * 32;
    av[j] = (f < KD) ? (f16u(araw[f]) + f16u(araw[144 + f])) : 0.f;
  }

  float bestval = -3.4e38f;
  int bestidx = 0x7fffffff;
  const uint32_t* cl = g_cand + (size_t)gq * NCAND;
  #pragma unroll
  for (int base = 0; base < 4; base++) {
    uint32_t e;
    if (base < 3) e = cl[base * 32 + lane];
    else e = (lane == 0) ? (uint32_t)(g_S[gq] + 1) : 0u;  // approx best
    unsigned mask = __ballot_sync(0xffffffffu, e != 0u);
    while (mask) {
      int src = __ffs(mask) - 1;
      mask &= mask - 1;
      int n = (int)__shfl_sync(0xffffffffu, e, src) - 1;
      const uint16_t* braw = g_raw_ref + ((size_t)b * LQ + n) * 288;
      float s = 0.f;
      #pragma unroll
      for (int j = 0; j < 5; j++) {
        int f = lane + j * 32;
        if (f < KD) s = fmaf(av[j], f16u(braw[f]) + f16u(braw[144 + f]), s);
      }
      #pragma unroll
      for (int o = 16; o; o >>= 1) s += __shfl_xor_sync(0xffffffffu, s, o);
      if (s > bestval || (s == bestval && n < bestidx)) {
        bestval = s; bestidx = n;
      }
    }
  }
  if (lane == 0) {
    g_S[gq] = bestidx;
    if (write_tail) out_tail[gq] = (float)bestidx;
  }
}

// ----------------------------------------------- gather + fold (fused) ------
__global__ __launch_bounds__(256) void fold_kernel(
    const float* __restrict__ org, float* __restrict__ out) {
  int b = blockIdx.z;
  int x = blockIdx.x * 16 + threadIdx.x;
  int y = blockIdx.y * 16 + threadIdx.y;
  int yp = y + 2, xp = x + 2;
  int myl = max(0, (yp - 4) / 2);
  int myh = min(95, yp >> 1);
  int mxl = max(0, (xp - 4) / 2);
  int mxh = min(95, xp >> 1);
  const int* Sb = g_S + b * LQ;

  int off[9];
  #pragma unroll
  for (int a = 0; a < 3; a++) {
    int my = myl + a;
    bool mok = (my <= myh);
    int myc = min(my, 95);
    int ki = yp - 2 * my;
    #pragma unroll
    for (int e = 0; e < 3; e++) {
      int mx = mxl + e;
      bool xok = (mx <= mxh);
      int mxc = min(mx, 95);
      int kj = xp - 2 * mx;
      int s = Sb[myc * 96 + mxc];
      int sy = s / 96;
      int sx = s - sy * 96;
      int gy = 2 * sy + ki - 2;
      int gx = 2 * sx + kj - 2;
      bool inb = mok & xok & (gy >= 0) & (gy < 192) & (gx >= 0) & (gx < 192);
      off[a * 3 + e] = inb ? (gy * 192 + gx) : -1;
    }
  }

  #pragma unroll 4
  for (int c = 0; c < 16; c++) {
    const float* oc = org + (size_t)((b * 16 + c) * 192) * 192;
    float sum = 0.f;
    #pragma unroll
    for (int u = 0; u < 9; u++)
      if (off[u] >= 0) sum += oc[off[u]];
    out[((b * 16 + c) * 192 + y) * 192 + x] = sum;
  }
}

// ------------------------------------------------------------------ host ----
extern "C" void kernel_launch(void* const* d_in, const int* in_sizes, int n_in,
                              void* d_out, int out_size) {
  (void)in_sizes; (void)n_in;
  const float* lrsr  = (const float*)d_in[0];
  const float* refsr = (const float*)d_in[1];
  const float* org   = (const float*)d_in[2];
  float* out = (float*)d_out;

  cudaFuncSetAttribute(argmax_mma, cudaFuncAttributeMaxDynamicSharedMemorySize,
                       SMEM_TOTAL);

  prep_kernel<<<(2 * BB * LQ * 32) / 256, 256>>>(lrsr, refsr);
  pack_kernel<<<dim3(BB * NT, 2), 256>>>();
  clear_kernel<<<(BB * LQ * NCAND + 255) / 256, 256>>>();
  argmax_mma<<<BB * NT, 384, SMEM_TOTAL>>>();
  int write_tail = (out_size >= TOUT + SOUT) ? 1 : 0;
  rescore_kernel<<<(BB * LQ + 7) / 8, 256>>>(out + TOUT, write_tail);
  fold_kernel<<<dim3(12, 12, BB), dim3(16, 16)>>>(org, out);
}

// round 12
// speedup vs baseline: 1.4820x; 1.4820x over previous
#include <cuda_runtime.h>
#include <cuda_fp16.h>
#include <cstdint>

#define LQ   9216
#define KD   144
#define CCH  16
#define HH   96
#define WW   96
#define BB   2
#define TOUT (BB*CCH*192*192) /* 1179648 */
#define SOUT (BB*LQ)          /* 18432   */
#define NT   72               /* tiles of 128 patches */
#define NKB  9                /* hi-only k16 blocks per tile */
#define TILE_U32 9216         /* packed u32 per tile image (9*1024) */
#define NCAND 96              /* per-query candidate slots: 16 writers x 6 */

__device__ __align__(16) uint16_t g_raw_lr [BB*LQ*288];
__device__ __align__(16) uint16_t g_raw_ref[BB*LQ*288];
__device__ float g_anorm[BB*LQ];
__device__ float g_bestv[BB*LQ];
__device__ __align__(16) uint32_t g_A[BB*NT*TILE_U32];
__device__ __align__(16) uint32_t g_B[BB*NT*TILE_U32];
__device__ __align__(16) uint2 g_cand[BB*LQ*NCAND];
__device__ int g_S[BB*LQ];

// ------------------------------------------------------------ PTX helpers ---
__device__ __forceinline__ uint32_t smem_u32(const void* p) {
  uint32_t a;
  asm("{ .reg .u64 t; cvta.to.shared.u64 t, %1; cvt.u32.u64 %0, t; }"
      : "=r"(a) : "l"(p));
  return a;
}
__device__ __forceinline__ void mbar_init(uint32_t a, uint32_t cnt) {
  asm volatile("mbarrier.init.shared.b64 [%0], %1;" :: "r"(a), "r"(cnt) : "memory");
}
__device__ __forceinline__ void mbar_arrive(uint32_t a) {
  asm volatile("mbarrier.arrive.shared.b64 _, [%0];" :: "r"(a) : "memory");
}
__device__ __forceinline__ void mbar_wait(uint32_t a, uint32_t parity) {
  asm volatile(
      "{\n\t.reg .pred P;\n\t"
      "WL_%=:\n\t"
      "mbarrier.try_wait.parity.acquire.cta.shared::cta.b64 P, [%0], %1, 0x989680;\n\t"
      "@P bra.uni WD_%=;\n\t"
      "bra.uni WL_%=;\n\t"
      "WD_%=:\n\t}"
      :: "r"(a), "r"(parity) : "memory");
}
__device__ __forceinline__ void cp16(uint32_t dst, const void* src) {
  asm volatile("cp.async.cg.shared.global [%0], [%1], 16;"
               :: "r"(dst), "l"(src) : "memory");
}
__device__ __forceinline__ void cp_commit() {
  asm volatile("cp.async.commit_group;" ::: "memory");
}
__device__ __forceinline__ void cp_wait0() {
  asm volatile("cp.async.wait_group 0;" ::: "memory");
}
__device__ __forceinline__ void mma_f16(float c[4], const uint32_t a[4],
                                        const uint32_t b[2]) {
  asm volatile(
      "mma.sync.aligned.m16n8k16.row.col.f32.f16.f16.f32 "
      "{%0,%1,%2,%3}, {%4,%5,%6,%7}, {%8,%9}, {%0,%1,%2,%3};"
      : "+f"(c[0]), "+f"(c[1]), "+f"(c[2]), "+f"(c[3])
      : "r"(a[0]), "r"(a[1]), "r"(a[2]), "r"(a[3]), "r"(b[0]), "r"(b[1]));
}
__device__ __forceinline__ void f16_split(float v, uint16_t& hi, uint16_t& lo) {
  uint16_t h;
  asm("cvt.rn.f16.f32 %0, %1;" : "=h"(h) : "f"(v));
  float hf;
  asm("cvt.f32.f16 %0, %1;" : "=f"(hf) : "h"(h));
  uint16_t l;
  asm("cvt.rn.f16.f32 %0, %1;" : "=h"(l) : "f"(v - hf));
  hi = h; lo = l;
}
__device__ __forceinline__ float f16u(uint16_t b) {
  float f;
  asm("cvt.f32.f16 %0, %1;" : "=f"(f) : "h"(b));
  return f;
}

// ---------------------------------------- prep: unfold + norm + fp16 split --
__global__ __launch_bounds__(256) void prep_kernel(
    const float* __restrict__ lrsr, const float* __restrict__ refsr) {
  int gw   = (blockIdx.x * 256 + threadIdx.x) >> 5;
  int lane = threadIdx.x & 31;
  if (gw >= 2 * BB * LQ) return;
  int sel = (gw >= BB * LQ) ? 1 : 0;
  int r = gw - sel * BB * LQ;
  int b = r / LQ, l = r - b * LQ;
  int y = l / WW, x = l - y * WW;
  const float* src = (sel ? refsr : lrsr) + (size_t)b * CCH * HH * WW;

  float v[5];
  float ss = 0.f;
  #pragma unroll
  for (int j = 0; j < 5; j++) {
    int f = lane + j * 32;
    float val = 0.f;
    if (f < KD) {
      int c = f / 9, k9 = f - c * 9, ki = k9 / 3, kj = k9 - ki * 3;
      int iy = y + ki - 1, ix = x + kj - 1;
      if (iy >= 0 && iy < HH && ix >= 0 && ix < WW)
        val = src[(c * HH + iy) * WW + ix];
    }
    v[j] = val;
    ss += val * val;
  }
  #pragma unroll
  for (int o = 16; o; o >>= 1) ss += __shfl_xor_sync(0xffffffffu, ss, o);
  uint16_t* dst;
  if (sel) {
    float inv = 1.0f / fmaxf(sqrtf(ss), 1e-12f);
    #pragma unroll
    for (int j = 0; j < 5; j++) v[j] *= inv;
    dst = g_raw_ref;
  } else {
    if (lane == 0) g_anorm[r] = sqrtf(ss);
    dst = g_raw_lr;
  }
  dst += (size_t)r * 288;
  #pragma unroll
  for (int j = 0; j < 5; j++) {
    int f = lane + j * 32;
    if (f < KD) {
      uint16_t h, lo;
      f16_split(v[j], h, lo);
      dst[f]       = h;
      dst[144 + f] = lo;
    }
  }
}

// ------------------------- pack hi blocks into m16n8k16 fragment layouts ----
__global__ __launch_bounds__(256) void pack_kernel() {
  int ti  = blockIdx.x;                  // b*NT + tile
  int isB = blockIdx.y;
  const uint32_t* raw32 = reinterpret_cast<const uint32_t*>(
      (isB ? g_raw_ref : g_raw_lr) + (size_t)ti * 128 * 288);
  uint4* dst = reinterpret_cast<uint4*>(
      (isB ? g_B : g_A) + (size_t)ti * TILE_U32);
  for (int o4 = threadIdx.x; o4 < TILE_U32 / 4; o4 += 256) {
    int kb = o4 >> 8, rr = o4 & 255;     // 256 uint4 per 4KB block, kb<9
    uint4 val;
    if (isB) {
      int c2 = rr & 1, n = rr >> 1;
      int q = n * 144 + kb * 8 + 2 * c2;
      val.x = raw32[q];     val.y = raw32[q + 4];
      val.z = raw32[q + 1]; val.w = raw32[q + 5];
    } else {
      int c = rr & 3, g = (rr >> 2) & 7, mg = rr >> 5;
      int m = mg * 16 + g;
      int q = kb * 8 + c;
      val.x = raw32[m * 144 + q];       val.y = raw32[(m + 8) * 144 + q];
      val.z = raw32[m * 144 + q + 4];   val.w = raw32[(m + 8) * 144 + q + 4];
    }
    dst[o4] = val;
  }
}

// -------------------------------------------------- clear candidate lists ---
__global__ __launch_bounds__(256) void clear_kernel() {
  int i = blockIdx.x * 256 + threadIdx.x;
  if (i < BB * LQ * NCAND) g_cand[i] = make_uint2(0u, 0u);
}

// ----------------------------- phase 1: hi-only argmax GEMM + candidates ----
#define SM_A   0          /* 36864 B: resident A hi image */
#define SM_B   36864      /* ring: 8 x 4096 B -> ends 69632 */
#define SM_MB  69632      /* mbarriers */
#define SM_RV  69760      /* 2048 B reduce vals */
#define SM_RI  71808      /* 2048 B reduce idx  */
#define SMEM_TOTAL 73856

__global__ __launch_bounds__(384, 1) void argmax_mma() {
  extern __shared__ __align__(16) char smem[];
  uint32_t sb = smem_u32(smem);
  int tid = threadIdx.x, wid = tid >> 5, lane = tid & 31;
  int cta = blockIdx.x;
  int b = cta / NT, qt = cta - b * NT;
  const uint32_t* Atile = g_A + (size_t)cta * TILE_U32;
  const uint32_t* Bbase = g_B + (size_t)b * NT * TILE_U32;

  uint32_t mb_full  = sb + SM_MB;        // 8 x 8B
  uint32_t mb_empty = sb + SM_MB + 64;   // 8 x 8B
  if (tid == 0) {
    for (int s = 0; s < 8; s++) {
      mbar_init(mb_full + 8 * s, 32);
      mbar_init(mb_empty + 8 * s, 256);
    }
  }
  for (int c = tid; c < TILE_U32 / 4; c += 384)
    cp16(sb + SM_A + c * 16, Atile + c * 4);
  cp_commit();
  cp_wait0();
  __syncthreads();

  if (wid >= 8) {
    int pw = wid - 8;
    for (int gblk = pw; gblk < NT * NKB; gblk += 4) {
      int s = gblk & 7, u = gblk >> 3;
      mbar_wait(mb_empty + 8 * s, (u & 1) ^ 1);
      const uint32_t* src = Bbase + (size_t)gblk * 1024;
      uint32_t slot = sb + SM_B + s * 4096;
      #pragma unroll
      for (int i = 0; i < 8; i++) {
        int c = i * 32 + lane;
        cp16(slot + c * 16, src + c * 4);
      }
      cp_commit();
      cp_wait0();
      mbar_arrive(mb_full + 8 * s);
    }
  } else {
    int wm = wid & 1, wn = (wid >> 1) & 3;
    float C[4][4][4];
    float bestv[8], margin[8];
    int besti[8], cnt[8];
    uint32_t candbase[8];
    #pragma unroll
    for (int sl = 0; sl < 8; sl++) {
      bestv[sl] = -3.4e38f; besti[sl] = 0; cnt[sl] = 0;
      int mf = sl >> 1, h = sl & 1;
      int m_local = wm * 64 + mf * 16 + (lane >> 2) + h * 8;
      int qg = b * LQ + qt * 128 + m_local;
      margin[sl] = 2e-3f * g_anorm[qg];
      candbase[sl] = (uint32_t)qg * NCAND + (wn * 4 + (lane & 3)) * 6;
    }

    uint32_t abase = sb + SM_A + (lane >> 2) * 64 + (lane & 3) * 16;
    uint32_t bbase = sb + SM_B + wn * 1024 + (lane >> 2) * 32 + (lane & 3) * 8;

    for (int t = 0; t < NT; t++) {
      #pragma unroll
      for (int mf = 0; mf < 4; mf++)
        #pragma unroll
        for (int nf = 0; nf < 4; nf++)
          #pragma unroll
          for (int c = 0; c < 4; c++) C[mf][nf][c] = 0.f;

      for (int kb = 0; kb < NKB; kb++) {
        int gblk = t * NKB + kb, s = gblk & 7, u = gblk >> 3;
        mbar_wait(mb_full + 8 * s, u & 1);
        uint32_t bslot = bbase + s * 4096;
        uint32_t breg[4][2];
        #pragma unroll
        for (int nf = 0; nf < 4; nf++)
          asm volatile("ld.shared.v2.b32 {%0,%1}, [%2];"
                       : "=r"(breg[nf][0]), "=r"(breg[nf][1])
                       : "r"(bslot + nf * 256));
        uint32_t areg[4][4];
        #pragma unroll
        for (int mf = 0; mf < 4; mf++)
          asm volatile("ld.shared.v4.b32 {%0,%1,%2,%3}, [%4];"
                       : "=r"(areg[mf][0]), "=r"(areg[mf][1]),
                         "=r"(areg[mf][2]), "=r"(areg[mf][3])
                       : "r"(abase + kb * 4096 + (wm * 4 + mf) * 512));
        #pragma unroll
        for (int mf = 0; mf < 4; mf++)
          #pragma unroll
          for (int nf = 0; nf < 4; nf++)
            mma_f16(C[mf][nf], areg[mf], breg[nf]);
        mbar_arrive(mb_empty + 8 * s);
      }
      // epilogue: branchless fmax tree, single guard per slot; slow path rare
      #pragma unroll
      for (int mf = 0; mf < 4; mf++) {
        #pragma unroll
        for (int h = 0; h < 2; h++) {
          int sl = mf * 2 + h;
          float smax = C[mf][0][h * 2];
          smax = fmaxf(smax, C[mf][0][h * 2 + 1]);
          smax = fmaxf(smax, fmaxf(C[mf][1][h * 2], C[mf][1][h * 2 + 1]));
          smax = fmaxf(smax, fmaxf(C[mf][2][h * 2], C[mf][2][h * 2 + 1]));
          smax = fmaxf(smax, fmaxf(C[mf][3][h * 2], C[mf][3][h * 2 + 1]));
          if (smax > bestv[sl] - margin[sl]) {
            #pragma unroll
            for (int nf = 0; nf < 4; nf++) {
              #pragma unroll
              for (int cl = 0; cl < 2; cl++) {
                float vv = C[mf][nf][h * 2 + cl];
                if (vv > bestv[sl] - margin[sl]) {
                  int n = t * 128 + wn * 32 + nf * 8 + (lane & 3) * 2 + cl;
                  g_cand[candbase[sl] + cnt[sl]] =
                      make_uint2(__float_as_uint(vv), (uint32_t)(n + 1));
                  cnt[sl] = (cnt[sl] == 5) ? 0 : cnt[sl] + 1;
                  if (vv > bestv[sl]) { bestv[sl] = vv; besti[sl] = n; }
                }
              }
            }
          }
        }
      }
    }
    // quad-lane reduce of approx best
    #pragma unroll
    for (int sl = 0; sl < 8; sl++) {
      float v = bestv[sl];
      int i = besti[sl];
      #pragma unroll
      for (int off = 1; off <= 2; off <<= 1) {
        float ov = __shfl_xor_sync(0xffffffffu, v, off);
        int oi = __shfl_xor_sync(0xffffffffu, i, off);
        if (ov > v || (ov == v && oi < i)) { v = ov; i = oi; }
      }
      bestv[sl] = v; besti[sl] = i;
    }
    if ((lane & 3) == 0) {
      float* rv = reinterpret_cast<float*>(smem + SM_RV);
      int* ri = reinterpret_cast<int*>(smem + SM_RI);
      #pragma unroll
      for (int sl = 0; sl < 8; sl++) {
        int m_local = wm * 64 + (sl >> 1) * 16 + (sl & 1) * 8 + (lane >> 2);
        rv[wn * 128 + m_local] = bestv[sl];
        ri[wn * 128 + m_local] = besti[sl];
      }
    }
  }

  __syncthreads();
  if (tid < 128) {
    const float* rv = reinterpret_cast<const float*>(smem + SM_RV);
    const int* ri = reinterpret_cast<const int*>(smem + SM_RI);
    float best = -3.4e38f; int bi = 0x7fffffff;
    #pragma unroll
    for (int wn = 0; wn < 4; wn++) {
      float v = rv[wn * 128 + tid];
      int i = ri[wn * 128 + tid];
      if (v > best || (v == best && i < bi)) { best = v; bi = i; }
    }
    g_S[b * LQ + qt * 128 + tid] = bi;
    g_bestv[b * LQ + qt * 128 + tid] = best;
  }
}

// ------------------------------ phase 2: exact fp32 rescore of candidates ---
__global__ __launch_bounds__(256) void rescore_kernel(
    float* __restrict__ out_tail, int write_tail) {
  int gq = blockIdx.x * 8 + (threadIdx.x >> 5);
  int lane = threadIdx.x & 31;
  if (gq >= BB * LQ) return;
  int b = gq / LQ;

  float bmax = g_bestv[gq];
  float marg = 2e-3f * g_anorm[gq];
  float thr = bmax - marg;

  // reconstruct query row a (exact fp32 = hi + lo)
  const uint16_t* araw = g_raw_lr + (size_t)gq * 288;
  float av[5];
  #pragma unroll
  for (int j = 0; j < 5; j++) {
    int f = lane + j * 32;
    av[j] = (f < KD) ? (f16u(araw[f]) + f16u(araw[144 + f])) : 0.f;
  }

  float bestval = -3.4e38f;
  int bestidx = 0x7fffffff;
  const uint2* cl = g_cand + (size_t)gq * NCAND;
  #pragma unroll
  for (int base = 0; base < 4; base++) {
    uint32_t e = 0u;
    if (base < 3) {
      uint2 c2 = cl[base * 32 + lane];
      if (c2.y != 0u && __uint_as_float(c2.x) >= thr) e = c2.y;
    } else {
      if (lane == 0) e = (uint32_t)(g_S[gq] + 1);  // approx best (evict-proof)
    }
    unsigned mask = __ballot_sync(0xffffffffu, e != 0u);
    while (mask) {
      int src = __ffs(mask) - 1;
      mask &= mask - 1;
      int n = (int)__shfl_sync(0xffffffffu, e, src) - 1;
      const uint16_t* braw = g_raw_ref + ((size_t)b * LQ + n) * 288;
      float s = 0.f;
      #pragma unroll
      for (int j = 0; j < 5; j++) {
        int f = lane + j * 32;
        if (f < KD) s = fmaf(av[j], f16u(braw[f]) + f16u(braw[144 + f]), s);
      }
      #pragma unroll
      for (int o = 16; o; o >>= 1) s += __shfl_xor_sync(0xffffffffu, s, o);
      if (s > bestval || (s == bestval && n < bestidx)) {
        bestval = s; bestidx = n;
      }
    }
  }
  if (lane == 0) {
    g_S[gq] = bestidx;
    if (write_tail) out_tail[gq] = (float)bestidx;
  }
}

// ----------------------------------------------- gather + fold (fused) ------
__global__ __launch_bounds__(256) void fold_kernel(
    const float* __restrict__ org, float* __restrict__ out) {
  int b = blockIdx.z;
  int x = blockIdx.x * 16 + threadIdx.x;
  int y = blockIdx.y * 16 + threadIdx.y;
  int yp = y + 2, xp = x + 2;
  int myl = max(0, (yp - 4) / 2);
  int myh = min(95, yp >> 1);
  int mxl = max(0, (xp - 4) / 2);
  int mxh = min(95, xp >> 1);
  const int* Sb = g_S + b * LQ;

  int off[9];
  #pragma unroll
  for (int a = 0; a < 3; a++) {
    int my = myl + a;
    bool mok = (my <= myh);
    int myc = min(my, 95);
    int ki = yp - 2 * my;
    #pragma unroll
    for (int e = 0; e < 3; e++) {
      int mx = mxl + e;
      bool xok = (mx <= mxh);
      int mxc = min(mx, 95);
      int kj = xp - 2 * mx;
      int s = Sb[myc * 96 + mxc];
      int sy = s / 96;
      int sx = s - sy * 96;
      int gy = 2 * sy + ki - 2;
      int gx = 2 * sx + kj - 2;
      bool inb = mok & xok & (gy >= 0) & (gy < 192) & (gx >= 0) & (gx < 192);
      off[a * 3 + e] = inb ? (gy * 192 + gx) : -1;
    }
  }

  #pragma unroll 4
  for (int c = 0; c < 16; c++) {
    const float* oc = org + (size_t)((b * 16 + c) * 192) * 192;
    float sum = 0.f;
    #pragma unroll
    for (int u = 0; u < 9; u++)
      if (off[u] >= 0) sum += oc[off[u]];
    out[((b * 16 + c) * 192 + y) * 192 + x] = sum;
  }
}

// ------------------------------------------------------------------ host ----
extern "C" void kernel_launch(void* const* d_in, const int* in_sizes, int n_in,
                              void* d_out, int out_size) {
  (void)in_sizes; (void)n_in;
  const float* lrsr  = (const float*)d_in[0];
  const float* refsr = (const float*)d_in[1];
  const float* org   = (const float*)d_in[2];
  float* out = (float*)d_out;

  cudaFuncSetAttribute(argmax_mma, cudaFuncAttributeMaxDynamicSharedMemorySize,
                       SMEM_TOTAL);

  prep_kernel<<<(2 * BB * LQ * 32) / 256, 256>>>(lrsr, refsr);
  pack_kernel<<<dim3(BB * NT, 2), 256>>>();
  clear_kernel<<<(BB * LQ * NCAND + 255) / 256, 256>>>();
  argmax_mma<<<BB * NT, 384, SMEM_TOTAL>>>();
  int write_tail = (out_size >= TOUT + SOUT) ? 1 : 0;
  rescore_kernel<<<(BB * LQ + 7) / 8, 256>>>(out + TOUT, write_tail);
  fold_kernel<<<dim3(12, 12, BB), dim3(16, 16)>>>(org, out);
}

// round 13
// speedup vs baseline: 1.6750x; 1.1302x over previous
#include <cuda_runtime.h>
#include <cuda_fp16.h>
#include <cstdint>

#define LQ   9216
#define KD   144
#define CCH  16
#define HH   96
#define WW   96
#define BB   2
#define TOUT (BB*CCH*192*192) /* 1179648 */
#define SOUT (BB*LQ)          /* 18432   */
#define NT   72               /* tiles of 128 patches */
#define NKB  9                /* hi-only k16 blocks per tile */
#define TILE_U32 9216         /* packed u32 per tile image (9*1024) */
#define NCAND 96              /* per-query candidate slots: 16 writers x 6 */

__device__ __align__(16) uint16_t g_raw_lr [BB*LQ*288];
__device__ __align__(16) uint16_t g_raw_ref[BB*LQ*288];
__device__ float g_anorm[BB*LQ];
__device__ float g_bestv[BB*LQ];
__device__ __align__(16) uint32_t g_A[BB*NT*TILE_U32];
__device__ __align__(16) uint32_t g_B[BB*NT*TILE_U32];
__device__ __align__(16) uint2 g_cand[BB*LQ*NCAND];
__device__ int g_S[BB*LQ];

// ------------------------------------------------------------ PTX helpers ---
__device__ __forceinline__ uint32_t smem_u32(const void* p) {
  uint32_t a;
  asm("{ .reg .u64 t; cvta.to.shared.u64 t, %1; cvt.u32.u64 %0, t; }"
      : "=r"(a) : "l"(p));
  return a;
}
__device__ __forceinline__ void mbar_init(uint32_t a, uint32_t cnt) {
  asm volatile("mbarrier.init.shared.b64 [%0], %1;" :: "r"(a), "r"(cnt) : "memory");
}
__device__ __forceinline__ void mbar_arrive(uint32_t a) {
  asm volatile("mbarrier.arrive.shared.b64 _, [%0];" :: "r"(a) : "memory");
}
__device__ __forceinline__ void mbar_wait(uint32_t a, uint32_t parity) {
  asm volatile(
      "{\n\t.reg .pred P;\n\t"
      "WL_%=:\n\t"
      "mbarrier.try_wait.parity.acquire.cta.shared::cta.b64 P, [%0], %1, 0x989680;\n\t"
      "@P bra.uni WD_%=;\n\t"
      "bra.uni WL_%=;\n\t"
      "WD_%=:\n\t}"
      :: "r"(a), "r"(parity) : "memory");
}
__device__ __forceinline__ void cp16(uint32_t dst, const void* src) {
  asm volatile("cp.async.cg.shared.global [%0], [%1], 16;"
               :: "r"(dst), "l"(src) : "memory");
}
__device__ __forceinline__ void cp_commit() {
  asm volatile("cp.async.commit_group;" ::: "memory");
}
__device__ __forceinline__ void cp_wait0() {
  asm volatile("cp.async.wait_group 0;" ::: "memory");
}
__device__ __forceinline__ void mma_f16(float c[4], const uint32_t a[4],
                                        const uint32_t b[2]) {
  asm volatile(
      "mma.sync.aligned.m16n8k16.row.col.f32.f16.f16.f32 "
      "{%0,%1,%2,%3}, {%4,%5,%6,%7}, {%8,%9}, {%0,%1,%2,%3};"
      : "+f"(c[0]), "+f"(c[1]), "+f"(c[2]), "+f"(c[3])
      : "r"(a[0]), "r"(a[1]), "r"(a[2]), "r"(a[3]), "r"(b[0]), "r"(b[1]));
}
__device__ __forceinline__ void f16_split(float v, uint16_t& hi, uint16_t& lo) {
  uint16_t h;
  asm("cvt.rn.f16.f32 %0, %1;" : "=h"(h) : "f"(v));
  float hf;
  asm("cvt.f32.f16 %0, %1;" : "=f"(hf) : "h"(h));
  uint16_t l;
  asm("cvt.rn.f16.f32 %0, %1;" : "=h"(l) : "f"(v - hf));
  hi = h; lo = l;
}
__device__ __forceinline__ float f16u(uint16_t b) {
  float f;
  asm("cvt.f32.f16 %0, %1;" : "=f"(f) : "h"(b));
  return f;
}

// ---------------------------------------- prep: unfold + norm + fp16 split --
__global__ __launch_bounds__(256) void prep_kernel(
    const float* __restrict__ lrsr, const float* __restrict__ refsr) {
  int gw   = (blockIdx.x * 256 + threadIdx.x) >> 5;
  int lane = threadIdx.x & 31;
  if (gw >= 2 * BB * LQ) return;
  int sel = (gw >= BB * LQ) ? 1 : 0;
  int r = gw - sel * BB * LQ;
  int b = r / LQ, l = r - b * LQ;
  int y = l / WW, x = l - y * WW;
  const float* src = (sel ? refsr : lrsr) + (size_t)b * CCH * HH * WW;

  float v[5];
  float ss = 0.f;
  #pragma unroll
  for (int j = 0; j < 5; j++) {
    int f = lane + j * 32;
    float val = 0.f;
    if (f < KD) {
      int c = f / 9, k9 = f - c * 9, ki = k9 / 3, kj = k9 - ki * 3;
      int iy = y + ki - 1, ix = x + kj - 1;
      if (iy >= 0 && iy < HH && ix >= 0 && ix < WW)
        val = src[(c * HH + iy) * WW + ix];
    }
    v[j] = val;
    ss += val * val;
  }
  #pragma unroll
  for (int o = 16; o; o >>= 1) ss += __shfl_xor_sync(0xffffffffu, ss, o);
  uint16_t* dst;
  if (sel) {
    float inv = 1.0f / fmaxf(sqrtf(ss), 1e-12f);
    #pragma unroll
    for (int j = 0; j < 5; j++) v[j] *= inv;
    dst = g_raw_ref;
  } else {
    if (lane == 0) g_anorm[r] = sqrtf(ss);
    dst = g_raw_lr;
  }
  dst += (size_t)r * 288;
  #pragma unroll
  for (int j = 0; j < 5; j++) {
    int f = lane + j * 32;
    if (f < KD) {
      uint16_t h, lo;
      f16_split(v[j], h, lo);
      dst[f]       = h;
      dst[144 + f] = lo;
    }
  }
}

// ------------------------- pack hi blocks into m16n8k16 fragment layouts ----
__global__ __launch_bounds__(256) void pack_kernel() {
  int ti  = blockIdx.x;                  // b*NT + tile
  int isB = blockIdx.y;
  const uint32_t* raw32 = reinterpret_cast<const uint32_t*>(
      (isB ? g_raw_ref : g_raw_lr) + (size_t)ti * 128 * 288);
  uint4* dst = reinterpret_cast<uint4*>(
      (isB ? g_B : g_A) + (size_t)ti * TILE_U32);
  for (int o4 = threadIdx.x; o4 < TILE_U32 / 4; o4 += 256) {
    int kb = o4 >> 8, rr = o4 & 255;     // 256 uint4 per 4KB block, kb<9
    uint4 val;
    if (isB) {
      int c2 = rr & 1, n = rr >> 1;
      int q = n * 144 + kb * 8 + 2 * c2;
      val.x = raw32[q];     val.y = raw32[q + 4];
      val.z = raw32[q + 1]; val.w = raw32[q + 5];
    } else {
      int c = rr & 3, g = (rr >> 2) & 7, mg = rr >> 5;
      int m = mg * 16 + g;
      int q = kb * 8 + c;
      val.x = raw32[m * 144 + q];       val.y = raw32[(m + 8) * 144 + q];
      val.z = raw32[m * 144 + q + 4];   val.w = raw32[(m + 8) * 144 + q + 4];
    }
    dst[o4] = val;
  }
}

// -------------------------------------------------- clear candidate lists ---
__global__ __launch_bounds__(256) void clear_kernel() {
  int i = blockIdx.x * 256 + threadIdx.x;
  if (i < BB * LQ * NCAND) g_cand[i] = make_uint2(0u, 0u);
}

// ----------------------------- phase 1: hi-only argmax GEMM + candidates ----
// SMEM: A image 36864 | B ring 3 x 36864 | mbarriers | reduce
#define SM_A   0
#define SM_B   36864
#define SM_MB  147456
#define SM_RV  147584
#define SM_RI  149632
#define SMEM_TOTAL 151680

__global__ __launch_bounds__(384, 1) void argmax_mma() {
  extern __shared__ __align__(16) char smem[];
  uint32_t sb = smem_u32(smem);
  int tid = threadIdx.x, wid = tid >> 5, lane = tid & 31;
  int cta = blockIdx.x;
  int b = cta / NT, qt = cta - b * NT;
  const uint32_t* Atile = g_A + (size_t)cta * TILE_U32;
  const uint32_t* Bbase = g_B + (size_t)b * NT * TILE_U32;

  uint32_t mb_full  = sb + SM_MB;        // 3 x 8B
  uint32_t mb_empty = sb + SM_MB + 64;   // 3 x 8B
  if (tid == 0) {
    for (int s = 0; s < 3; s++) {
      mbar_init(mb_full + 8 * s, 128);   // 4 producer warps x 32 lanes
      mbar_init(mb_empty + 8 * s, 256);  // 8 compute warps x 32 lanes
    }
  }
  for (int c = tid; c < TILE_U32 / 4; c += 384)
    cp16(sb + SM_A + c * 16, Atile + c * 4);
  cp_commit();
  cp_wait0();
  __syncthreads();

  if (wid >= 8) {
    // ---- producers: 4 warps cooperatively fill one whole tile per slot ----
    int pw = wid - 8;
    for (int t = 0; t < NT; t++) {
      int s = t % 3, u = t / 3;
      mbar_wait(mb_empty + 8 * s, (u & 1) ^ 1);
      const uint32_t* src = Bbase + (size_t)t * TILE_U32 + pw * 2304;
      uint32_t slot = sb + SM_B + s * 36864 + pw * 9216;
      #pragma unroll
      for (int i = 0; i < 18; i++) {
        int c = i * 32 + lane;
        cp16(slot + c * 16, src + c * 4);
      }
      cp_commit();
      cp_wait0();
      mbar_arrive(mb_full + 8 * s);
    }
  } else {
    int wm = wid & 1, wn = (wid >> 1) & 3;
    float C[4][4][4];
    float bestv[8], margin[8];
    int besti[8], cnt[8];
    uint32_t candbase[8];
    #pragma unroll
    for (int sl = 0; sl < 8; sl++) {
      bestv[sl] = -3.4e38f; besti[sl] = 0; cnt[sl] = 0;
      int mf = sl >> 1, h = sl & 1;
      int m_local = wm * 64 + mf * 16 + (lane >> 2) + h * 8;
      int qg = b * LQ + qt * 128 + m_local;
      margin[sl] = 2e-3f * g_anorm[qg];
      candbase[sl] = (uint32_t)qg * NCAND + (wn * 4 + (lane & 3)) * 6;
    }

    uint32_t abase = sb + SM_A + (lane >> 2) * 64 + (lane & 3) * 16;
    uint32_t bbase = sb + SM_B + wn * 1024 + (lane >> 2) * 32 + (lane & 3) * 8;

    for (int t = 0; t < NT; t++) {
      int s = t % 3, u = t / 3;
      #pragma unroll
      for (int mf = 0; mf < 4; mf++)
        #pragma unroll
        for (int nf = 0; nf < 4; nf++)
          #pragma unroll
          for (int c = 0; c < 4; c++) C[mf][nf][c] = 0.f;

      mbar_wait(mb_full + 8 * s, u & 1);
      uint32_t bslot0 = bbase + s * 36864;
      #pragma unroll 3
      for (int kb = 0; kb < NKB; kb++) {
        uint32_t breg[4][2];
        #pragma unroll
        for (int nf = 0; nf < 4; nf++)
          asm volatile("ld.shared.v2.b32 {%0,%1}, [%2];"
                       : "=r"(breg[nf][0]), "=r"(breg[nf][1])
                       : "r"(bslot0 + kb * 4096 + nf * 256));
        uint32_t areg[4][4];
        #pragma unroll
        for (int mf = 0; mf < 4; mf++)
          asm volatile("ld.shared.v4.b32 {%0,%1,%2,%3}, [%4];"
                       : "=r"(areg[mf][0]), "=r"(areg[mf][1]),
                         "=r"(areg[mf][2]), "=r"(areg[mf][3])
                       : "r"(abase + kb * 4096 + (wm * 4 + mf) * 512));
        #pragma unroll
        for (int mf = 0; mf < 4; mf++)
          #pragma unroll
          for (int nf = 0; nf < 4; nf++)
            mma_f16(C[mf][nf], areg[mf], breg[nf]);
      }
      mbar_arrive(mb_empty + 8 * s);

      // epilogue: branchless fmax tree, single guard per slot; slow path rare
      #pragma unroll
      for (int mf = 0; mf < 4; mf++) {
        #pragma unroll
        for (int h = 0; h < 2; h++) {
          int sl = mf * 2 + h;
          float smax = C[mf][0][h * 2];
          smax = fmaxf(smax, C[mf][0][h * 2 + 1]);
          smax = fmaxf(smax, fmaxf(C[mf][1][h * 2], C[mf][1][h * 2 + 1]));
          smax = fmaxf(smax, fmaxf(C[mf][2][h * 2], C[mf][2][h * 2 + 1]));
          smax = fmaxf(smax, fmaxf(C[mf][3][h * 2], C[mf][3][h * 2 + 1]));
          if (smax > bestv[sl] - margin[sl]) {
            #pragma unroll
            for (int nf = 0; nf < 4; nf++) {
              #pragma unroll
              for (int cl = 0; cl < 2; cl++) {
                float vv = C[mf][nf][h * 2 + cl];
                if (vv > bestv[sl] - margin[sl]) {
                  int n = t * 128 + wn * 32 + nf * 8 + (lane & 3) * 2 + cl;
                  g_cand[candbase[sl] + cnt[sl]] =
                      make_uint2(__float_as_uint(vv), (uint32_t)(n + 1));
                  cnt[sl] = (cnt[sl] == 5) ? 0 : cnt[sl] + 1;
                  if (vv > bestv[sl]) { bestv[sl] = vv; besti[sl] = n; }
                }
              }
            }
          }
        }
      }
    }
    // quad-lane reduce of approx best
    #pragma unroll
    for (int sl = 0; sl < 8; sl++) {
      float v = bestv[sl];
      int i = besti[sl];
      #pragma unroll
      for (int off = 1; off <= 2; off <<= 1) {
        float ov = __shfl_xor_sync(0xffffffffu, v, off);
        int oi = __shfl_xor_sync(0xffffffffu, i, off);
        if (ov > v || (ov == v && oi < i)) { v = ov; i = oi; }
      }
      bestv[sl] = v; besti[sl] = i;
    }
    if ((lane & 3) == 0) {
      float* rv = reinterpret_cast<float*>(smem + SM_RV);
      int* ri = reinterpret_cast<int*>(smem + SM_RI);
      #pragma unroll
      for (int sl = 0; sl < 8; sl++) {
        int m_local = wm * 64 + (sl >> 1) * 16 + (sl & 1) * 8 + (lane >> 2);
        rv[wn * 128 + m_local] = bestv[sl];
        ri[wn * 128 + m_local] = besti[sl];
      }
    }
  }

  __syncthreads();
  if (tid < 128) {
    const float* rv = reinterpret_cast<const float*>(smem + SM_RV);
    const int* ri = reinterpret_cast<const int*>(smem + SM_RI);
    float best = -3.4e38f; int bi = 0x7fffffff;
    #pragma unroll
    for (int wn = 0; wn < 4; wn++) {
      float v = rv[wn * 128 + tid];
      int i = ri[wn * 128 + tid];
      if (v > best || (v == best && i < bi)) { best = v; bi = i; }
    }
    g_S[b * LQ + qt * 128 + tid] = bi;
    g_bestv[b * LQ + qt * 128 + tid] = best;
  }
}

// ------------------------------ phase 2: exact fp32 rescore of candidates ---
__global__ __launch_bounds__(256) void rescore_kernel(
    float* __restrict__ out_tail, int write_tail) {
  int gq = blockIdx.x * 8 + (threadIdx.x >> 5);
  int lane = threadIdx.x & 31;
  if (gq >= BB * LQ) return;
  int b = gq / LQ;

  float bmax = g_bestv[gq];
  float marg = 2e-3f * g_anorm[gq];
  float thr = bmax - marg;

  // reconstruct query row a (exact fp32 = hi + lo)
  const uint16_t* araw = g_raw_lr + (size_t)gq * 288;
  float av[5];
  #pragma unroll
  for (int j = 0; j < 5; j++) {
    int f = lane + j * 32;
    av[j] = (f < KD) ? (f16u(araw[f]) + f16u(araw[144 + f])) : 0.f;
  }

  float bestval = -3.4e38f;
  int bestidx = 0x7fffffff;
  const uint2* cl = g_cand + (size_t)gq * NCAND;
  #pragma unroll
  for (int base = 0; base < 4; base++) {
    uint32_t e = 0u;
    if (base < 3) {
      uint2 c2 = cl[base * 32 + lane];
      if (c2.y != 0u && __uint_as_float(c2.x) >= thr) e = c2.y;
    } else {
      if (lane == 0) e = (uint32_t)(g_S[gq] + 1);  // approx best (evict-proof)
    }
    unsigned mask = __ballot_sync(0xffffffffu, e != 0u);
    while (mask) {
      int src = __ffs(mask) - 1;
      mask &= mask - 1;
      int n = (int)__shfl_sync(0xffffffffu, e, src) - 1;
      const uint16_t* braw = g_raw_ref + ((size_t)b * LQ + n) * 288;
      float s = 0.f;
      #pragma unroll
      for (int j = 0; j < 5; j++) {
        int f = lane + j * 32;
        if (f < KD) s = fmaf(av[j], f16u(braw[f]) + f16u(braw[144 + f]), s);
      }
      #pragma unroll
      for (int o = 16; o; o >>= 1) s += __shfl_xor_sync(0xffffffffu, s, o);
      if (s > bestval || (s == bestval && n < bestidx)) {
        bestval = s; bestidx = n;
      }
    }
  }
  if (lane == 0) {
    g_S[gq] = bestidx;
    if (write_tail) out_tail[gq] = (float)bestidx;
  }
}

// ----------------------------------------------- gather + fold (fused) ------
__global__ __launch_bounds__(256) void fold_kernel(
    const float* __restrict__ org, float* __restrict__ out) {
  int b = blockIdx.z;
  int x = blockIdx.x * 16 + threadIdx.x;
  int y = blockIdx.y * 16 + threadIdx.y;
  int yp = y + 2, xp = x + 2;
  int myl = max(0, (yp - 4) / 2);
  int myh = min(95, yp >> 1);
  int mxl = max(0, (xp - 4) / 2);
  int mxh = min(95, xp >> 1);
  const int* Sb = g_S + b * LQ;

  int off[9];
  #pragma unroll
  for (int a = 0; a < 3; a++) {
    int my = myl + a;
    bool mok = (my <= myh);
    int myc = min(my, 95);
    int ki = yp - 2 * my;
    #pragma unroll
    for (int e = 0; e < 3; e++) {
      int mx = mxl + e;
      bool xok = (mx <= mxh);
      int mxc = min(mx, 95);
      int kj = xp - 2 * mx;
      int s = Sb[myc * 96 + mxc];
      int sy = s / 96;
      int sx = s - sy * 96;
      int gy = 2 * sy + ki - 2;
      int gx = 2 * sx + kj - 2;
      bool inb = mok & xok & (gy >= 0) & (gy < 192) & (gx >= 0) & (gx < 192);
      off[a * 3 + e] = inb ? (gy * 192 + gx) : -1;
    }
  }

  #pragma unroll 4
  for (int c = 0; c < 16; c++) {
    const float* oc = org + (size_t)((b * 16 + c) * 192) * 192;
    float sum = 0.f;
    #pragma unroll
    for (int u = 0; u < 9; u++)
      if (off[u] >= 0) sum += oc[off[u]];
    out[((b * 16 + c) * 192 + y) * 192 + x] = sum;
  }
}

// ------------------------------------------------------------------ host ----
extern "C" void kernel_launch(void* const* d_in, const int* in_sizes, int n_in,
                              void* d_out, int out_size) {
  (void)in_sizes; (void)n_in;
  const float* lrsr  = (const float*)d_in[0];
  const float* refsr = (const float*)d_in[1];
  const float* org   = (const float*)d_in[2];
  float* out = (float*)d_out;

  cudaFuncSetAttribute(argmax_mma, cudaFuncAttributeMaxDynamicSharedMemorySize,
                       SMEM_TOTAL);

  prep_kernel<<<(2 * BB * LQ * 32) / 256, 256>>>(lrsr, refsr);
  pack_kernel<<<dim3(BB * NT, 2), 256>>>();
  clear_kernel<<<(BB * LQ * NCAND + 255) / 256, 256>>>();
  argmax_mma<<<BB * NT, 384, SMEM_TOTAL>>>();
  int write_tail = (out_size >= TOUT + SOUT) ? 1 : 0;
  rescore_kernel<<<(BB * LQ + 7) / 8, 256>>>(out + TOUT, write_tail);
  fold_kernel<<<dim3(12, 12, BB), dim3(16, 16)>>>(org, out);
}